// round 4
// baseline (speedup 1.0000x reference)
#include <cuda_runtime.h>
#include <math.h>

#define H 64
#define W 64
#define C 256
#define P 7
#define NUM_ROIS 256
#define FC (W * C)   // floats per x-row

__device__ __forceinline__ float4 fmax4(float4 a, float4 b) {
    a.x = fmaxf(a.x, b.x);
    a.y = fmaxf(a.y, b.y);
    a.z = fmaxf(a.z, b.z);
    a.w = fmaxf(a.w, b.w);
    return a;
}

// One block per (roi, i). 256 threads:
//   tid & 63 : float4 channel group (c = (tid&63)*4)
//   tid >> 6 : pair-slot ps; handles bins jA=ps and jB=ps+4 (ps<3) fused.
// Both bins share x rows, so each inner iteration issues 4 independent loads
// (2 y-positions x 2 bins) -> MLP 4 with (almost) no duplicate loads.
__global__ __launch_bounds__(256) void roi_pool_kernel(
    const float* __restrict__ feat,   // (H, W, C)
    const float* __restrict__ rois,   // (NUM_ROIS, 4) = x1,y1,x2,y2
    float* __restrict__ out)          // (NUM_ROIS, P, P, C)
{
    const int b = blockIdx.x;         // r*P + i
    const int r = b / P;
    const int i = b - r * P;

    const float x1 = __ldg(&rois[r * 4 + 0]);
    const float y1 = __ldg(&rois[r * 4 + 1]);
    const float x2 = __ldg(&rois[r * 4 + 2]);
    const float y2 = __ldg(&rois[r * 4 + 3]);

    // x (H) bin bounds — exact reference math. With 0<=x1<x2<=1 these are
    // provably in-range: xs in [0,63], xs+xlen <= 64, xlen >= 1.
    const int lox   = (int)floorf(x1 * (float)H);
    const int hix   = (int)ceilf(x2 * (float)H);
    const int spanx = max(hix - lox, 1);
    const int xs    = lox + (i * spanx) / P;
    const int xe    = lox + ((i + 1) * spanx + (P - 1)) / P;
    const int xlen  = max(xe - xs, 1);

    // y (W) span
    const int loy   = (int)floorf(y1 * (float)W);
    const int hiy   = (int)ceilf(y2 * (float)W);
    const int spany = max(hiy - loy, 1);

    const int ps = threadIdx.x >> 6;              // 0..3
    const int c4 = (threadIdx.x & 63) << 2;       // float4 channel offset
    const int jA = ps;
    const int jB = (ps < 3) ? ps + 4 : ps;        // ps==3: B duplicates A

    const int ysA   = loy + (jA * spany) / P;
    const int yeA   = loy + ((jA + 1) * spany + (P - 1)) / P;
    const int lenA  = max(yeA - ysA, 1);
    const int ysB   = loy + (jB * spany) / P;
    const int yeB   = loy + ((jB + 1) * spany + (P - 1)) / P;
    const int lenB  = max(yeB - ysB, 1);

    const int lastA = lenA - 1;
    const int lastB = lenB - 1;
    const int smax  = max(lenA, lenB);

    const float NEG = -INFINITY;
    float4 aA0 = make_float4(NEG, NEG, NEG, NEG);
    float4 aA1 = aA0, aB0 = aA0, aB1 = aA0;

    const float* rowp = feat + (size_t)xs * FC + c4;

    for (int sx = 0; sx < xlen; ++sx) {
        for (int s = 0; s < smax; s += 2) {
            const int s1  = s + 1;
            const int yA0 = ysA + min(s,  lastA);
            const int yA1 = ysA + min(s1, lastA);
            const int yB0 = ysB + min(s,  lastB);
            const int yB1 = ysB + min(s1, lastB);
            const float4 vA0 = *reinterpret_cast<const float4*>(rowp + yA0 * C);
            const float4 vA1 = *reinterpret_cast<const float4*>(rowp + yA1 * C);
            const float4 vB0 = *reinterpret_cast<const float4*>(rowp + yB0 * C);
            const float4 vB1 = *reinterpret_cast<const float4*>(rowp + yB1 * C);
            aA0 = fmax4(aA0, vA0);
            aA1 = fmax4(aA1, vA1);
            aB0 = fmax4(aB0, vB0);
            aB1 = fmax4(aB1, vB1);
        }
        rowp += FC;
    }

    const float4 aA = fmax4(aA0, aA1);

    float* opA = out + (((size_t)(r * P + i) * P + jA) * C) + c4;
    *reinterpret_cast<float4*>(opA) = aA;

    if (ps < 3) {
        const float4 aB = fmax4(aB0, aB1);
        float* opB = out + (((size_t)(r * P + i) * P + jB) * C) + c4;
        *reinterpret_cast<float4*>(opB) = aB;
    }
}

extern "C" void kernel_launch(void* const* d_in, const int* in_sizes, int n_in,
                              void* d_out, int out_size) {
    const float* feat = (const float*)d_in[0];
    const float* rois = (const float*)d_in[1];
    if (n_in >= 2 && in_sizes[0] == NUM_ROIS * 4 && in_sizes[1] == H * W * C) {
        feat = (const float*)d_in[1];
        rois = (const float*)d_in[0];
    }
    float* out = (float*)d_out;

    roi_pool_kernel<<<NUM_ROIS * P, 256>>>(feat, rois, out);
}

// round 5
// speedup vs baseline: 1.4095x; 1.4095x over previous
#include <cuda_runtime.h>
#include <math.h>

#define H 64
#define W 64
#define C 256
#define P 7
#define NUM_ROIS 256
#define FC (W * C)   // floats per x-row (16384)

__device__ __forceinline__ float4 fmax4(float4 a, float4 b) {
    a.x = fmaxf(a.x, b.x);
    a.y = fmaxf(a.y, b.y);
    a.z = fmaxf(a.z, b.z);
    a.w = fmaxf(a.w, b.w);
    return a;
}

// Block = (roi, i), 224 threads = 7 warps; warp w computes bin j = w.
// Lane l owns channels [l*4, l*4+4) and [128 + l*4, 128 + l*4 + 4):
// both warp loads are fully-coalesced 512B. y unrolled x2 (tail clamped,
// max-safe, L1-hit) -> 4 independent load streams per lane.
__global__ __launch_bounds__(224) void roi_pool_kernel(
    const float* __restrict__ feat,   // (H, W, C)
    const float* __restrict__ rois,   // (NUM_ROIS, 4) = x1,y1,x2,y2
    float* __restrict__ out)          // (NUM_ROIS, P, P, C)
{
    const int b = blockIdx.x;         // r*P + i
    const int r = b / P;
    const int i = b - r * P;

    const int j    = (int)threadIdx.x >> 5;   // warp id = y-bin (0..6)
    const int lane = (int)threadIdx.x & 31;
    const int c0   = lane << 2;               // first channel quad
    // second quad at c0 + 128 (byte offset +512)

    const float x1 = __ldg(&rois[r * 4 + 0]);
    const float y1 = __ldg(&rois[r * 4 + 1]);
    const float x2 = __ldg(&rois[r * 4 + 2]);
    const float y2 = __ldg(&rois[r * 4 + 3]);

    // x (H) bin bounds — exact reference math; provably in-range for
    // 0 <= x1 < x2 <= 1 (xs in [0,63], xs+xlen <= 64, xlen >= 1).
    const int lox   = (int)floorf(x1 * (float)H);
    const int hix   = (int)ceilf(x2 * (float)H);
    const int spanx = max(hix - lox, 1);
    const int xs    = lox + (i * spanx) / P;
    const int xe    = lox + ((i + 1) * spanx + (P - 1)) / P;
    const int xlen  = max(xe - xs, 1);

    // y (W) bin bounds for this warp's j
    const int loy   = (int)floorf(y1 * (float)W);
    const int hiy   = (int)ceilf(y2 * (float)W);
    const int spany = max(hiy - loy, 1);
    const int ys    = loy + (j * spany) / P;
    const int ye    = loy + ((j + 1) * spany + (P - 1)) / P;
    const int ylen  = max(ye - ys, 1);
    const int ylast = ylen - 1;

    const float NEG = -INFINITY;
    float4 aL0 = make_float4(NEG, NEG, NEG, NEG);
    float4 aL1 = aL0, aH0 = aL0, aH1 = aL0;

    // base pointer at (xs, ys, c0)
    const float* rowp = feat + (size_t)xs * FC + (size_t)ys * C + c0;

    for (int sx = 0; sx < xlen; ++sx) {
        const float* p = rowp;
        for (int s = 0; s < ylen; s += 2) {
            const int d1 = min(s + 1, ylast) - s;   // 0 or 1
            const float4 vL0 = *reinterpret_cast<const float4*>(p);
            const float4 vH0 = *reinterpret_cast<const float4*>(p + 128);
            const float4 vL1 = *reinterpret_cast<const float4*>(p + d1 * C);
            const float4 vH1 = *reinterpret_cast<const float4*>(p + d1 * C + 128);
            aL0 = fmax4(aL0, vL0);
            aH0 = fmax4(aH0, vH0);
            aL1 = fmax4(aL1, vL1);
            aH1 = fmax4(aH1, vH1);
            p += 2 * C;
        }
        rowp += FC;
    }

    const float4 aL = fmax4(aL0, aL1);
    const float4 aH = fmax4(aH0, aH1);

    float* op = out + (((size_t)(r * P + i) * P + j) * C) + c0;
    *reinterpret_cast<float4*>(op)       = aL;
    *reinterpret_cast<float4*>(op + 128) = aH;
}

extern "C" void kernel_launch(void* const* d_in, const int* in_sizes, int n_in,
                              void* d_out, int out_size) {
    const float* feat = (const float*)d_in[0];
    const float* rois = (const float*)d_in[1];
    if (n_in >= 2 && in_sizes[0] == NUM_ROIS * 4 && in_sizes[1] == H * W * C) {
        feat = (const float*)d_in[1];
        rois = (const float*)d_in[0];
    }
    float* out = (float*)d_out;

    roi_pool_kernel<<<NUM_ROIS * P, 224>>>(feat, rois, out);
}